// round 1
// baseline (speedup 1.0000x reference)
#include <cuda_runtime.h>
#include <math.h>

// Problem constants (from reference setup_inputs)
#define BB 4
#define LL 4092
#define HH 8
#define DH 64
#define DM 512          // H*Dh
#define WS 12
#define STEP 6
#define NW 681          // (L - OV) / STEP
#define MROWS (BB*LL*HH)   // 130944 token-head rows
#define LNEPS 1e-5f

// ---------------- scratch (static device globals; no allocation) -------------
__device__ float g_Qp[BB*HH*LL*DH];   // projected Q, layout [B,H,L,Dh]
__device__ float g_Kp[BB*HH*LL*DH];
__device__ float g_Vp[BB*HH*LL*DH];
__device__ float g_ow[BB*HH*NW*WS*DH]; // per-window attention outputs

// =============================================================================
// Kernel 1: token-wise projections.  X:[M,64] (M = B*L*H, layout [B,L,H,64]
// is already contiguous rows) times W^T (64x64), three matrices.
// Output scattered to [B,H,L,64] layout so windows become contiguous.
// Block: 256 threads = 16x16, each thread computes a 4x4 tile of a 64x64 block.
// =============================================================================
__global__ __launch_bounds__(256) void proj_kernel(
    const float* __restrict__ q, const float* __restrict__ k, const float* __restrict__ v,
    const float* __restrict__ Wq, const float* __restrict__ Wk, const float* __restrict__ Wv)
{
    __shared__ float Wt[64*64];      // transposed: Wt[d*64+e] = W[e*64+d]
    __shared__ float Xs[64*68];      // padded rows (68) to avoid bank conflicts

    const int tid = threadIdx.x;
    const int tx = tid & 15;         // e-tile
    const int ty = tid >> 4;         // row-tile
    const int r0 = blockIdx.x * 64;  // first global row of this tile

    const float* Xsrc[3] = {q, k, v};
    const float* Wsrc[3] = {Wq, Wk, Wv};
    float* Outp[3] = {g_Qp, g_Kp, g_Vp};

    for (int m = 0; m < 3; m++) {
        // load W transposed (coalesced read, scattered smem write; one-time)
        const float* W = Wsrc[m];
        for (int idx = tid; idx < 4096; idx += 256) {
            int e = idx >> 6, d = idx & 63;
            Wt[d*64 + e] = W[idx];
        }
        // load 64x64 X tile as float4 into padded smem
        const float* X = Xsrc[m] + (size_t)r0 * 64;
        for (int idx = tid; idx < 1024; idx += 256) {     // 1024 float4
            int row = idx >> 4, c4 = idx & 15;
            float4 val = reinterpret_cast<const float4*>(X)[row*16 + c4];
            *reinterpret_cast<float4*>(&Xs[row*68 + c4*4]) = val;
        }
        __syncthreads();

        float acc[4][4];
        #pragma unroll
        for (int i = 0; i < 4; i++)
            #pragma unroll
            for (int j = 0; j < 4; j++) acc[i][j] = 0.f;

        #pragma unroll 8
        for (int d = 0; d < 64; d++) {
            float xr[4];
            #pragma unroll
            for (int i = 0; i < 4; i++) xr[i] = Xs[(ty*4 + i)*68 + d];
            float4 wv = *reinterpret_cast<const float4*>(&Wt[d*64 + tx*4]);
            #pragma unroll
            for (int i = 0; i < 4; i++) {
                acc[i][0] = fmaf(xr[i], wv.x, acc[i][0]);
                acc[i][1] = fmaf(xr[i], wv.y, acc[i][1]);
                acc[i][2] = fmaf(xr[i], wv.z, acc[i][2]);
                acc[i][3] = fmaf(xr[i], wv.w, acc[i][3]);
            }
        }

        // write: decode (b,l,h) from row, scatter to [B,H,L,64]
        float* Out = Outp[m];
        #pragma unroll
        for (int i = 0; i < 4; i++) {
            int r = r0 + ty*4 + i;
            int b = r / (LL*HH);
            int rem = r - b*(LL*HH);
            int l = rem >> 3;         // /H (H==8)
            int h = rem & 7;
            size_t orow = ((size_t)(b*HH + h)*LL + l)*64;
            float4 o = make_float4(acc[i][0], acc[i][1], acc[i][2], acc[i][3]);
            *reinterpret_cast<float4*>(&Out[orow + tx*4]) = o;
        }
        __syncthreads();
    }
}

// =============================================================================
// Kernel 2: per-window attention. One block (128 threads) per (b,h,n) window.
// Windows are contiguous 12x64 blocks in the [B,H,L,64] projected layout.
// =============================================================================
__global__ __launch_bounds__(128) void attn_kernel(float* __restrict__ attn_out)
{
    __shared__ float Qs[WS*68];
    __shared__ float Ks[WS*68];
    __shared__ float Vs[WS*68];
    __shared__ float P[WS*WS];

    const int tid = threadIdx.x;
    const int widx = blockIdx.x;          // (b*H + h)*NW + n
    const int n = widx % NW;
    const int bh = widx / NW;
    const size_t base = ((size_t)bh * LL + n*STEP) * 64;   // 12 contiguous rows

    // load Q/K/V window tiles (contiguous 768 floats each) into padded smem
    {
        const float* srcs[3] = {g_Qp + base, g_Kp + base, g_Vp + base};
        float* dsts[3] = {Qs, Ks, Vs};
        for (int idx = tid; idx < 3*192; idx += 128) {   // 192 float4 per tile
            int m = idx / 192, rem = idx - m*192;
            int row = rem >> 4, c4 = rem & 15;
            float4 val = reinterpret_cast<const float4*>(srcs[m])[rem];
            *reinterpret_cast<float4*>(&dsts[m][row*68 + c4*4]) = val;
        }
    }
    __syncthreads();

    // scores -> P (store pre-softmax scaled scores)
    for (int o = tid; o < 144; o += 128) {
        int qi = o / 12, ki = o - qi*12;
        const float* qr = &Qs[qi*68];
        const float* kr = &Ks[ki*68];
        float s = 0.f;
        #pragma unroll
        for (int d = 0; d < 64; d += 4) {
            float4 a = *reinterpret_cast<const float4*>(&qr[d]);
            float4 b = *reinterpret_cast<const float4*>(&kr[d]);
            s = fmaf(a.x, b.x, s); s = fmaf(a.y, b.y, s);
            s = fmaf(a.z, b.z, s); s = fmaf(a.w, b.w, s);
        }
        P[o] = s * 0.125f;   // 1/sqrt(64)
    }
    __syncthreads();

    // softmax per row (12 rows, threads 0..11)
    if (tid < 12) {
        float* row = &P[tid*12];
        float mx = row[0];
        #pragma unroll
        for (int k2 = 1; k2 < 12; k2++) mx = fmaxf(mx, row[k2]);
        float sum = 0.f;
        float e[12];
        #pragma unroll
        for (int k2 = 0; k2 < 12; k2++) { e[k2] = __expf(row[k2] - mx); sum += e[k2]; }
        float inv = 1.f / sum;
        #pragma unroll
        for (int k2 = 0; k2 < 12; k2++) row[k2] = e[k2] * inv;
    }
    __syncthreads();

    // write attn probabilities (coalesced)
    if (attn_out) {
        for (int o = tid; o < 144; o += 128)
            attn_out[(size_t)widx*144 + o] = P[o];
    }

    // ow[q][e] = sum_k P[q][k] * V[k][e]
    float* owp = &g_ow[(size_t)widx * (WS*DH)];
    for (int o = tid; o < WS*DH; o += 128) {
        int qi = o >> 6, e = o & 63;
        const float* prow = &P[qi*12];
        float s = 0.f;
        #pragma unroll
        for (int k2 = 0; k2 < 12; k2++)
            s = fmaf(prow[k2], Vs[k2*68 + e], s);
        owp[o] = s;
    }
}

// =============================================================================
// Kernel 3: overlap-add average + residual + LayerNorm. One block per token.
// 128 threads, 4 channels each (float4).
// =============================================================================
__global__ __launch_bounds__(128) void combine_kernel(
    const float* __restrict__ queries, const float* __restrict__ gamma,
    const float* __restrict__ beta, float* __restrict__ z)
{
    __shared__ float red[8];

    const int tid = threadIdx.x;
    const int tok = blockIdx.x;
    const int b = tok / LL;
    const int t = tok - b*LL;
    const int c0 = tid * 4;
    const int h = c0 >> 6;
    const int e = c0 & 63;

    const int n1 = t / 6, w1 = t - n1*6;
    const int n0 = n1 - 1, w0 = w1 + 6;

    float4 acc = make_float4(0.f, 0.f, 0.f, 0.f);
    float cnt = 0.f;
    if (n1 < NW) {
        const float* p = &g_ow[(((size_t)(b*HH + h)*NW + n1)*WS + w1)*64 + e];
        float4 v = *reinterpret_cast<const float4*>(p);
        acc.x += v.x; acc.y += v.y; acc.z += v.z; acc.w += v.w; cnt += 1.f;
    }
    if (n0 >= 0) {
        const float* p = &g_ow[(((size_t)(b*HH + h)*NW + n0)*WS + w0)*64 + e];
        float4 v = *reinterpret_cast<const float4*>(p);
        acc.x += v.x; acc.y += v.y; acc.z += v.z; acc.w += v.w; cnt += 1.f;
    }
    float inv = 1.f / cnt;
    float4 resid = *reinterpret_cast<const float4*>(&queries[(size_t)tok*DM + c0]);
    float4 x;
    x.x = acc.x*inv + resid.x; x.y = acc.y*inv + resid.y;
    x.z = acc.z*inv + resid.z; x.w = acc.w*inv + resid.w;

    // block reduction for mean / var over 512 channels
    float s  = x.x + x.y + x.z + x.w;
    float ss = x.x*x.x + x.y*x.y + x.z*x.z + x.w*x.w;
    #pragma unroll
    for (int off = 16; off > 0; off >>= 1) {
        s  += __shfl_down_sync(0xFFFFFFFFu, s, off);
        ss += __shfl_down_sync(0xFFFFFFFFu, ss, off);
    }
    int wid = tid >> 5, lane = tid & 31;
    if (lane == 0) { red[wid] = s; red[4 + wid] = ss; }
    __syncthreads();
    float ts  = red[0] + red[1] + red[2] + red[3];
    float tss = red[4] + red[5] + red[6] + red[7];
    float mean = ts * (1.f / DM);
    float var  = tss * (1.f / DM) - mean*mean;
    float rstd = rsqrtf(var + LNEPS);

    float4 g = *reinterpret_cast<const float4*>(&gamma[c0]);
    float4 bta = *reinterpret_cast<const float4*>(&beta[c0]);
    float4 o;
    o.x = (x.x - mean)*rstd*g.x + bta.x;
    o.y = (x.y - mean)*rstd*g.y + bta.y;
    o.z = (x.z - mean)*rstd*g.z + bta.z;
    o.w = (x.w - mean)*rstd*g.w + bta.w;
    *reinterpret_cast<float4*>(&z[(size_t)tok*DM + c0]) = o;
}

// =============================================================================
extern "C" void kernel_launch(void* const* d_in, const int* in_sizes, int n_in,
                              void* d_out, int out_size) {
    const float* queries = (const float*)d_in[0];
    const float* keys    = (const float*)d_in[1];
    const float* values  = (const float*)d_in[2];
    const float* Wq      = (const float*)d_in[3];
    const float* Wk      = (const float*)d_in[4];
    const float* Wv      = (const float*)d_in[5];
    const float* gamma   = (const float*)d_in[6];
    const float* beta    = (const float*)d_in[7];

    float* z = (float*)d_out;
    const long Z = (long)BB * LL * DM;                 // 8,380,416
    const long A = (long)BB * HH * NW * WS * WS;       // 3,138,048
    float* attn_out = nullptr;
    if ((long)out_size >= Z + A) attn_out = z + Z;

    proj_kernel<<<MROWS/64, 256>>>(queries, keys, values, Wq, Wk, Wv);
    attn_kernel<<<BB*HH*NW, 128>>>(attn_out);
    combine_kernel<<<BB*LL, 128>>>(queries, gamma, beta, z);
}

// round 2
// speedup vs baseline: 1.1037x; 1.1037x over previous
#include <cuda_runtime.h>
#include <math.h>

// Problem constants
#define BB 4
#define LL 4092
#define HH 8
#define DH 64
#define DM 512
#define WS 12
#define STEP 6
#define NW 681
#define MROWS (BB*LL*HH)   // 130944
#define LNEPS 1e-5f
#define WB 8               // windows per attention block
#define NBLK_BH ((NW + WB - 1) / WB)   // 86

// ---------------- scratch -----------------
__device__ float g_Qp[BB*HH*LL*DH];
__device__ float g_Kp[BB*HH*LL*DH];
__device__ float g_Vp[BB*HH*LL*DH];
__device__ float g_ow[BB*HH*NW*WS*DH];

// =============================================================================
// Kernel 1: projections, 128 rows x 64 cols per block, 128 threads,
// 8x8 per-thread register tile. X transposed in smem for conflict-free LDS.128.
//   Xt: [64][136]  (Xt[d][row] = X[row][d])
//   Wt: [64][68]   (Wt[d][e]   = W[e][d])
// smem = (64*136 + 64*68) * 4 = 52224 bytes (dynamic)
// =============================================================================
__global__ __launch_bounds__(128) void proj_kernel(
    const float* __restrict__ q, const float* __restrict__ k, const float* __restrict__ v,
    const float* __restrict__ Wq, const float* __restrict__ Wk, const float* __restrict__ Wv)
{
    extern __shared__ float sm[];
    float* Xt = sm;                 // 64*136
    float* Wt = sm + 64*136;        // 64*68

    const int tid = threadIdx.x;
    const int lane = tid & 31;
    const int seg  = tid >> 5;      // 0..3 : which 16-float chunk of a row
    const int rt = tid >> 3;        // 0..15 row-tile
    const int ct = tid & 7;         // 0..7  col-tile
    const int r0 = blockIdx.x * 128;

    const float* Xsrc[3] = {q, k, v};
    const float* Wsrc[3] = {Wq, Wk, Wv};
    float* Outp[3] = {g_Qp, g_Kp, g_Vp};

    for (int m = 0; m < 3; m++) {
        // ---- load W transposed: thread reads W[e][d4*4..+3], writes 4 scalars
        {
            const float* W = Wsrc[m];
            for (int idx = tid; idx < 1024; idx += 128) {   // 1024 float4
                int e = idx & 63, d4 = idx >> 6;
                float4 wv = reinterpret_cast<const float4*>(W)[e*16 + d4];
                Wt[(d4*4+0)*68 + e] = wv.x;
                Wt[(d4*4+1)*68 + e] = wv.y;
                Wt[(d4*4+2)*68 + e] = wv.z;
                Wt[(d4*4+3)*68 + e] = wv.w;
            }
        }
        // ---- load X transposed: each iteration: 32 rows, warp 'seg' loads its
        // 64B chunk of each row (coalesced); STS conflict-free (consecutive rows)
        {
            const float* X = Xsrc[m];
            #pragma unroll
            for (int it = 0; it < 4; it++) {
                int row = lane + 32*it;
                const float4* src = reinterpret_cast<const float4*>(
                    X + (size_t)(r0 + row)*64 + seg*16);
                float4 a = src[0], b = src[1], c = src[2], d = src[3];
                int db = seg*16;
                Xt[(db+ 0)*136 + row] = a.x; Xt[(db+ 1)*136 + row] = a.y;
                Xt[(db+ 2)*136 + row] = a.z; Xt[(db+ 3)*136 + row] = a.w;
                Xt[(db+ 4)*136 + row] = b.x; Xt[(db+ 5)*136 + row] = b.y;
                Xt[(db+ 6)*136 + row] = b.z; Xt[(db+ 7)*136 + row] = b.w;
                Xt[(db+ 8)*136 + row] = c.x; Xt[(db+ 9)*136 + row] = c.y;
                Xt[(db+10)*136 + row] = c.z; Xt[(db+11)*136 + row] = c.w;
                Xt[(db+12)*136 + row] = d.x; Xt[(db+13)*136 + row] = d.y;
                Xt[(db+14)*136 + row] = d.z; Xt[(db+15)*136 + row] = d.w;
            }
        }
        __syncthreads();

        // ---- compute 8x8 tile
        float acc[8][8];
        #pragma unroll
        for (int i = 0; i < 8; i++)
            #pragma unroll
            for (int j = 0; j < 8; j++) acc[i][j] = 0.f;

        #pragma unroll 4
        for (int d = 0; d < 64; d++) {
            float4 xa = *reinterpret_cast<const float4*>(&Xt[d*136 + rt*8]);
            float4 xb = *reinterpret_cast<const float4*>(&Xt[d*136 + rt*8 + 4]);
            float4 wa = *reinterpret_cast<const float4*>(&Wt[d*68 + ct*8]);
            float4 wb = *reinterpret_cast<const float4*>(&Wt[d*68 + ct*8 + 4]);
            float xv[8] = {xa.x, xa.y, xa.z, xa.w, xb.x, xb.y, xb.z, xb.w};
            float wv[8] = {wa.x, wa.y, wa.z, wa.w, wb.x, wb.y, wb.z, wb.w};
            #pragma unroll
            for (int i = 0; i < 8; i++)
                #pragma unroll
                for (int j = 0; j < 8; j++)
                    acc[i][j] = fmaf(xv[i], wv[j], acc[i][j]);
        }

        // ---- store to [B,H,L,64] layout
        float* Out = Outp[m];
        #pragma unroll
        for (int i = 0; i < 8; i++) {
            int r = r0 + rt*8 + i;
            int b = r / (LL*HH);
            int rem = r - b*(LL*HH);
            int l = rem >> 3;
            int h = rem & 7;
            size_t orow = ((size_t)(b*HH + h)*LL + l)*64;
            *reinterpret_cast<float4*>(&Out[orow + ct*8]) =
                make_float4(acc[i][0], acc[i][1], acc[i][2], acc[i][3]);
            *reinterpret_cast<float4*>(&Out[orow + ct*8 + 4]) =
                make_float4(acc[i][4], acc[i][5], acc[i][6], acc[i][7]);
        }
        __syncthreads();
    }
}

// =============================================================================
// Kernel 2: attention, WB=8 windows per block (shared halo rows), 256 threads.
// smem: Qs/Ks/Vs [54][68] + P [WB][144] = 48672 bytes (dynamic)
// =============================================================================
__global__ __launch_bounds__(256) void attn_kernel(float* __restrict__ attn_out)
{
    extern __shared__ float sm[];
    float* Qs = sm;                 // 54*68
    float* Ks = Qs + 54*68;
    float* Vs = Ks + 54*68;
    float* P  = Vs + 54*68;         // WB*144

    const int tid = threadIdx.x;
    const int blk = blockIdx.x;
    const int bh = blk / NBLK_BH;
    const int ng = blk - bh * NBLK_BH;
    const int n0 = ng * WB;
    const int nwin = (NW - n0 < WB) ? (NW - n0) : WB;
    const int rows = nwin*6 + 6;    // token span of this window group

    const size_t base = ((size_t)bh * LL + n0*STEP) * 64;

    // ---- load Q/K/V spans (contiguous in [B,H,L,64])
    {
        const float* srcs[3] = {g_Qp + base, g_Kp + base, g_Vp + base};
        float* dsts[3] = {Qs, Ks, Vs};
        int nf4 = rows * 16;
        #pragma unroll
        for (int m = 0; m < 3; m++) {
            const float4* src = reinterpret_cast<const float4*>(srcs[m]);
            float* dst = dsts[m];
            for (int idx = tid; idx < nf4; idx += 256) {
                int row = idx >> 4, c4 = idx & 15;
                float4 val = src[idx];
                *reinterpret_cast<float4*>(&dst[row*68 + c4*4]) = val;
            }
        }
    }
    __syncthreads();

    // ---- scores
    for (int o = tid; o < nwin*144; o += 256) {
        int w = o / 144;
        int r = o - w*144;
        int qi = r / 12, ki = r - qi*12;
        const float* qr = &Qs[(w*6 + qi)*68];
        const float* kr = &Ks[(w*6 + ki)*68];
        float s = 0.f;
        #pragma unroll
        for (int d = 0; d < 64; d += 4) {
            float4 a = *reinterpret_cast<const float4*>(&qr[d]);
            float4 b = *reinterpret_cast<const float4*>(&kr[d]);
            s = fmaf(a.x, b.x, s); s = fmaf(a.y, b.y, s);
            s = fmaf(a.z, b.z, s); s = fmaf(a.w, b.w, s);
        }
        P[o] = s * 0.125f;
    }
    __syncthreads();

    // ---- softmax (one thread per (w, qi) row)
    for (int t = tid; t < nwin*12; t += 256) {
        int w = t / 12, qi = t - w*12;
        float* row = &P[w*144 + qi*12];
        float mx = row[0];
        #pragma unroll
        for (int k2 = 1; k2 < 12; k2++) mx = fmaxf(mx, row[k2]);
        float sum = 0.f;
        float e[12];
        #pragma unroll
        for (int k2 = 0; k2 < 12; k2++) { e[k2] = __expf(row[k2] - mx); sum += e[k2]; }
        float inv = 1.f / sum;
        #pragma unroll
        for (int k2 = 0; k2 < 12; k2++) row[k2] = e[k2] * inv;
    }
    __syncthreads();

    // ---- write attention probabilities (layout matches: windows consecutive)
    if (attn_out) {
        float* dst = attn_out + ((size_t)bh*NW + n0)*144;
        for (int o = tid; o < nwin*144; o += 256) dst[o] = P[o];
    }

    // ---- P @ V
    float* owp = &g_ow[((size_t)bh*NW + n0) * (WS*DH)];
    for (int o = tid; o < nwin*WS*DH; o += 256) {
        int w = o / (WS*DH);
        int r = o - w*(WS*DH);
        int qi = r >> 6, e = r & 63;
        const float* prow = &P[w*144 + qi*12];
        const float* vb = &Vs[(w*6)*68 + e];
        float s = 0.f;
        #pragma unroll
        for (int k2 = 0; k2 < 12; k2++)
            s = fmaf(prow[k2], vb[k2*68], s);
        owp[o] = s;
    }
}

// =============================================================================
// Kernel 3: overlap-add average + residual + LayerNorm (unchanged)
// =============================================================================
__global__ __launch_bounds__(128) void combine_kernel(
    const float* __restrict__ queries, const float* __restrict__ gamma,
    const float* __restrict__ beta, float* __restrict__ z)
{
    __shared__ float red[8];

    const int tid = threadIdx.x;
    const int tok = blockIdx.x;
    const int b = tok / LL;
    const int t = tok - b*LL;
    const int c0 = tid * 4;
    const int h = c0 >> 6;
    const int e = c0 & 63;

    const int n1 = t / 6, w1 = t - n1*6;
    const int n0 = n1 - 1, w0 = w1 + 6;

    float4 acc = make_float4(0.f, 0.f, 0.f, 0.f);
    float cnt = 0.f;
    if (n1 < NW) {
        const float* p = &g_ow[(((size_t)(b*HH + h)*NW + n1)*WS + w1)*64 + e];
        float4 v = *reinterpret_cast<const float4*>(p);
        acc.x += v.x; acc.y += v.y; acc.z += v.z; acc.w += v.w; cnt += 1.f;
    }
    if (n0 >= 0) {
        const float* p = &g_ow[(((size_t)(b*HH + h)*NW + n0)*WS + w0)*64 + e];
        float4 v = *reinterpret_cast<const float4*>(p);
        acc.x += v.x; acc.y += v.y; acc.z += v.z; acc.w += v.w; cnt += 1.f;
    }
    float inv = 1.f / cnt;
    float4 resid = *reinterpret_cast<const float4*>(&queries[(size_t)tok*DM + c0]);
    float4 x;
    x.x = acc.x*inv + resid.x; x.y = acc.y*inv + resid.y;
    x.z = acc.z*inv + resid.z; x.w = acc.w*inv + resid.w;

    float s  = x.x + x.y + x.z + x.w;
    float ss = x.x*x.x + x.y*x.y + x.z*x.z + x.w*x.w;
    #pragma unroll
    for (int off = 16; off > 0; off >>= 1) {
        s  += __shfl_down_sync(0xFFFFFFFFu, s, off);
        ss += __shfl_down_sync(0xFFFFFFFFu, ss, off);
    }
    int wid = tid >> 5, lane = tid & 31;
    if (lane == 0) { red[wid] = s; red[4 + wid] = ss; }
    __syncthreads();
    float ts  = red[0] + red[1] + red[2] + red[3];
    float tss = red[4] + red[5] + red[6] + red[7];
    float mean = ts * (1.f / DM);
    float var  = tss * (1.f / DM) - mean*mean;
    float rstd = rsqrtf(var + LNEPS);

    float4 g = *reinterpret_cast<const float4*>(&gamma[c0]);
    float4 bta = *reinterpret_cast<const float4*>(&beta[c0]);
    float4 o;
    o.x = (x.x - mean)*rstd*g.x + bta.x;
    o.y = (x.y - mean)*rstd*g.y + bta.y;
    o.z = (x.z - mean)*rstd*g.z + bta.z;
    o.w = (x.w - mean)*rstd*g.w + bta.w;
    *reinterpret_cast<float4*>(&z[(size_t)tok*DM + c0]) = o;
}

// =============================================================================
extern "C" void kernel_launch(void* const* d_in, const int* in_sizes, int n_in,
                              void* d_out, int out_size) {
    const float* queries = (const float*)d_in[0];
    const float* keys    = (const float*)d_in[1];
    const float* values  = (const float*)d_in[2];
    const float* Wq      = (const float*)d_in[3];
    const float* Wk      = (const float*)d_in[4];
    const float* Wv      = (const float*)d_in[5];
    const float* gamma   = (const float*)d_in[6];
    const float* beta    = (const float*)d_in[7];

    float* z = (float*)d_out;
    const long Z = (long)BB * LL * DM;
    const long A = (long)BB * HH * NW * WS * WS;
    float* attn_out = nullptr;
    if ((long)out_size >= Z + A) attn_out = z + Z;

    const int proj_smem = (64*136 + 64*68) * 4;             // 52224
    const int attn_smem = (3*54*68 + WB*144) * 4;           // 48672
    static bool attr_set = false;
    if (!attr_set) {
        cudaFuncSetAttribute(proj_kernel, cudaFuncAttributeMaxDynamicSharedMemorySize, proj_smem);
        cudaFuncSetAttribute(attn_kernel, cudaFuncAttributeMaxDynamicSharedMemorySize, attn_smem);
        attr_set = true;
    }

    proj_kernel<<<MROWS/128, 128, proj_smem>>>(queries, keys, values, Wq, Wk, Wv);
    attn_kernel<<<BB*HH*NBLK_BH, 256, attn_smem>>>(attn_out);
    combine_kernel<<<BB*LL, 128>>>(queries, gamma, beta, z);
}